// round 11
// baseline (speedup 1.0000x reference)
#include <cuda_runtime.h>
#include <cuda_bf16.h>
#include <cstdint>

// 2D DCT-II (4096x4096) as two NT GEMMs on mma.sync (HMMA) tensor cores.
//   T = gemm_nt(D, X);  Y = gemm_nt(D, T);   C[i][j] = sum_k A[i][k]*B[j][k]
// fp32 emulated via bf16 split: C = Ah*Bh + Ah*Bl + Al*Bh (fp32 reg accum).
// R11: 512 threads / CTA, 128x256 tile (16 warps) to lift tensor-pipe
// occupancy from 8 -> 16 warps/SM.

constexpr int MN = 4096;
constexpr int BM = 128, BN = 256, BK = 32;
constexpr int NC = MN / BK;  // 128 k-iterations
constexpr int STAGES = 3;

constexpr uint32_t ROWB = 80;             // 64B data + 16B pad (conflict-free ldmatrix)
constexpr uint32_t A_TILE_B = 128 * ROWB; // 10240
constexpr uint32_t B_TILE_B = 256 * ROWB; // 20480
constexpr uint32_t OFF_AH = 0;
constexpr uint32_t OFF_AL = A_TILE_B;
constexpr uint32_t OFF_BH = 2 * A_TILE_B;
constexpr uint32_t OFF_BL = 2 * A_TILE_B + B_TILE_B;
constexpr uint32_t STAGE_B = 2 * A_TILE_B + 2 * B_TILE_B;  // 61440
constexpr uint32_t SMEM_SZ = STAGES * STAGE_B;             // 184320

// raw-bf16 global scratch (ushort bit patterns)
__device__ __align__(256) unsigned short g_Dhi[(size_t)MN * MN];
__device__ __align__(256) unsigned short g_Dlo[(size_t)MN * MN];
__device__ __align__(256) unsigned short g_Xhi[(size_t)MN * MN];
__device__ __align__(256) unsigned short g_Xlo[(size_t)MN * MN];
__device__ __align__(256) unsigned short g_Thi[(size_t)MN * MN];
__device__ __align__(256) unsigned short g_Tlo[(size_t)MN * MN];

// ---------------- PTX helpers ----------------
__device__ __forceinline__ uint32_t smem_u32(const void* p) {
    uint32_t a;
    asm("{ .reg .u64 t; cvta.to.shared.u64 t, %1; cvt.u32.u64 %0, t; }" : "=r"(a) : "l"(p));
    return a;
}
__device__ __forceinline__ void cp16(uint32_t dst, const void* src) {
    asm volatile("cp.async.cg.shared.global [%0], [%1], 16;" ::"r"(dst), "l"(src) : "memory");
}
__device__ __forceinline__ void cp_commit() { asm volatile("cp.async.commit_group;" ::: "memory"); }
__device__ __forceinline__ void cp_wait1() { asm volatile("cp.async.wait_group 1;" ::: "memory"); }

__device__ __forceinline__ void ldsm4(uint32_t* r, uint32_t addr) {
    asm volatile("ldmatrix.sync.aligned.m8n8.x4.shared.b16 {%0,%1,%2,%3}, [%4];"
                 : "=r"(r[0]), "=r"(r[1]), "=r"(r[2]), "=r"(r[3])
                 : "r"(addr));
}
__device__ __forceinline__ void mma_bf16(float* c, const uint32_t* a, uint32_t b0, uint32_t b1) {
    asm volatile(
        "mma.sync.aligned.m16n8k16.row.col.f32.bf16.bf16.f32 "
        "{%0,%1,%2,%3}, {%4,%5,%6,%7}, {%8,%9}, {%0,%1,%2,%3};"
        : "+f"(c[0]), "+f"(c[1]), "+f"(c[2]), "+f"(c[3])
        : "r"(a[0]), "r"(a[1]), "r"(a[2]), "r"(a[3]), "r"(b0), "r"(b1));
}

// ---------------- fill / convert ----------------
__device__ __forceinline__ void split_bf16(float v, unsigned short& h, unsigned short& l) {
    __nv_bfloat16 bh = __float2bfloat16_rn(v);
    float fh = __bfloat162float(bh);
    __nv_bfloat16 bl = __float2bfloat16_rn(v - fh);
    h = __bfloat16_as_ushort(bh);
    l = __bfloat16_as_ushort(bl);
}

__global__ void fill_dct_split_kernel() {
    unsigned idx = blockIdx.x * blockDim.x + threadIdx.x;
    unsigned i4 = idx * 4;
    unsigned k = i4 >> 12;
    unsigned m0 = i4 & (MN - 1);
    unsigned short h[4], l[4];
#pragma unroll
    for (int j = 0; j < 4; j++) {
        unsigned m = m0 + j;
        unsigned t = (k * (2u * m + 1u)) & (4u * MN - 1u);
        float c = cospif((float)t * (1.0f / (2.0f * (float)MN)));
        split_bf16(c, h[j], l[j]);
    }
    uint2 ph = make_uint2((uint32_t)h[0] | ((uint32_t)h[1] << 16),
                          (uint32_t)h[2] | ((uint32_t)h[3] << 16));
    uint2 pl = make_uint2((uint32_t)l[0] | ((uint32_t)l[1] << 16),
                          (uint32_t)l[2] | ((uint32_t)l[3] << 16));
    ((uint2*)g_Dhi)[idx] = ph;
    ((uint2*)g_Dlo)[idx] = pl;
}

__global__ void convert_x_kernel(const float* __restrict__ x) {
    unsigned idx = blockIdx.x * blockDim.x + threadIdx.x;
    float4 v = ((const float4*)x)[idx];
    unsigned short h[4], l[4];
    split_bf16(v.x, h[0], l[0]);
    split_bf16(v.y, h[1], l[1]);
    split_bf16(v.z, h[2], l[2]);
    split_bf16(v.w, h[3], l[3]);
    uint2 ph = make_uint2((uint32_t)h[0] | ((uint32_t)h[1] << 16),
                          (uint32_t)h[2] | ((uint32_t)h[3] << 16));
    uint2 pl = make_uint2((uint32_t)l[0] | ((uint32_t)l[1] << 16),
                          (uint32_t)l[2] | ((uint32_t)l[3] << 16));
    ((uint2*)g_Xhi)[idx] = ph;
    ((uint2*)g_Xlo)[idx] = pl;
}

// ---------------- GEMM ----------------
// MODE 0: B = Xsplit, C -> Tsplit (bf16 hi/lo)
// MODE 1: B = Tsplit, C -> out (fp32)
template <int MODE>
__global__ void __launch_bounds__(512, 1) dct_gemm_kernel(float* __restrict__ out) {
    extern __shared__ __align__(128) char smem[];
    const uint32_t sbase = smem_u32(smem);
    const int tid = threadIdx.x;
    const int lane = tid & 31;
    const int wid = tid >> 5;  // 0..15
    const int wm = wid & 1;    // 2 warps along M (64 rows each)
    const int wn = wid >> 1;   // 8 warps along N (32 cols each)
    const int ntile = blockIdx.x;
    const int mtile = blockIdx.y;

    const unsigned short* __restrict__ Ah = g_Dhi;
    const unsigned short* __restrict__ Al = g_Dlo;
    const unsigned short* __restrict__ Bh = (MODE == 0) ? g_Xhi : g_Thi;
    const unsigned short* __restrict__ Bl = (MODE == 0) ? g_Xlo : g_Tlo;

    // ---- loader geometry ----
    // A: 128 rows x 4 chunks = 512 x 16B -> one per thread (hi and lo)
    const int arow = tid >> 2;  // 0..127
    const int ac = tid & 3;
    const uint32_t ad = (uint32_t)arow * ROWB + (uint32_t)ac * 16;
    const size_t aoff = (size_t)(mtile * BM + arow) * MN + ac * 8;
    // B: 256 rows x 4 chunks = 1024 -> two adjacent chunks per thread
    const int brow = tid >> 1;  // 0..255
    const int bc = (tid & 1) * 2;
    const uint32_t bd = (uint32_t)brow * ROWB + (uint32_t)bc * 16;
    const size_t boff = (size_t)(ntile * BN + brow) * MN + bc * 8;

    auto load_iter = [&](int it, int s) {
        const uint32_t sb = sbase + (uint32_t)s * STAGE_B;
        const size_t ko = (size_t)it * BK;
        cp16(sb + OFF_AH + ad, Ah + aoff + ko);
        cp16(sb + OFF_AL + ad, Al + aoff + ko);
        cp16(sb + OFF_BH + bd, Bh + boff + ko);
        cp16(sb + OFF_BH + bd + 16, Bh + boff + ko + 8);
        cp16(sb + OFF_BL + bd, Bl + boff + ko);
        cp16(sb + OFF_BL + bd + 16, Bl + boff + ko + 8);
    };

    // ---- ldmatrix per-lane address offsets ----
    const int mt = lane >> 3;
    // A x4: mat0=(m0-7,k0-7) mat1=(m8-15,k0-7) mat2=(m0-7,k8-15) mat3=(m8-15,k8-15)
    const uint32_t a_off = (uint32_t)(wm * 64 + (mt & 1) * 8 + (lane & 7)) * ROWB +
                           (uint32_t)((mt >> 1) * 16);
    // B x4: mat0=(n0-7,k0-7) mat1=(n0-7,k8-15) mat2=(n8-15,k0-7) mat3=(n8-15,k8-15)
    const uint32_t b_off = (uint32_t)(wn * 32 + (mt >> 1) * 8 + (lane & 7)) * ROWB +
                           (uint32_t)((mt & 1) * 16);

    float acc[4][4][4];
#pragma unroll
    for (int i = 0; i < 4; i++)
#pragma unroll
        for (int j = 0; j < 4; j++)
#pragma unroll
            for (int q = 0; q < 4; q++) acc[i][j][q] = 0.0f;

    // prologue: stages 0,1 in flight
    load_iter(0, 0);
    cp_commit();
    load_iter(1, 1);
    cp_commit();

    for (int it = 0; it < NC; ++it) {
        cp_wait1();       // iter `it` data resident (this thread's copies)
        __syncthreads();  // visible to all; all warps done with stage (it-1)%S

        if (it + 2 < NC) load_iter(it + 2, (it + 2) % STAGES);
        cp_commit();  // empty groups near the end keep wait accounting uniform

        const uint32_t sb = sbase + (uint32_t)(it % STAGES) * STAGE_B;
#pragma unroll
        for (int ks = 0; ks < 2; ks++) {
            const uint32_t ck = (uint32_t)ks * 32;
            uint32_t ah[4][4], al[4][4];
#pragma unroll
            for (int mi = 0; mi < 4; mi++) {
                ldsm4(ah[mi], sb + OFF_AH + a_off + (uint32_t)mi * (16 * ROWB) + ck);
                ldsm4(al[mi], sb + OFF_AL + a_off + (uint32_t)mi * (16 * ROWB) + ck);
            }
            uint32_t bh[2][4], bl[2][4];
#pragma unroll
            for (int bp = 0; bp < 2; bp++) {
                ldsm4(bh[bp], sb + OFF_BH + b_off + (uint32_t)bp * (16 * ROWB) + ck);
                ldsm4(bl[bp], sb + OFF_BL + b_off + (uint32_t)bp * (16 * ROWB) + ck);
            }
#pragma unroll
            for (int mi = 0; mi < 4; mi++)
#pragma unroll
                for (int ni = 0; ni < 4; ni++) {
                    const int bp = ni >> 1, pr = (ni & 1) * 2;
                    mma_bf16(acc[mi][ni], ah[mi], bh[bp][pr], bh[bp][pr + 1]);
                    mma_bf16(acc[mi][ni], ah[mi], bl[bp][pr], bl[bp][pr + 1]);
                    mma_bf16(acc[mi][ni], al[mi], bh[bp][pr], bh[bp][pr + 1]);
                }
        }
    }

    // ---- epilogue ----
    const int g = lane >> 2;
    const int cpair = (lane & 3) * 2;
#pragma unroll
    for (int mi = 0; mi < 4; mi++) {
#pragma unroll
        for (int ni = 0; ni < 4; ni++) {
            const int r0 = mtile * BM + wm * 64 + mi * 16 + g;
            const int r1 = r0 + 8;
            const int col = ntile * BN + wn * 32 + ni * 8 + cpair;
            if (MODE == 0) {
                unsigned short h0, l0, h1, l1;
                split_bf16(acc[mi][ni][0], h0, l0);
                split_bf16(acc[mi][ni][1], h1, l1);
                *(uint32_t*)(g_Thi + (size_t)r0 * MN + col) = (uint32_t)h0 | ((uint32_t)h1 << 16);
                *(uint32_t*)(g_Tlo + (size_t)r0 * MN + col) = (uint32_t)l0 | ((uint32_t)l1 << 16);
                split_bf16(acc[mi][ni][2], h0, l0);
                split_bf16(acc[mi][ni][3], h1, l1);
                *(uint32_t*)(g_Thi + (size_t)r1 * MN + col) = (uint32_t)h0 | ((uint32_t)h1 << 16);
                *(uint32_t*)(g_Tlo + (size_t)r1 * MN + col) = (uint32_t)l0 | ((uint32_t)l1 << 16);
            } else {
                *(float2*)(out + (size_t)r0 * MN + col) =
                    make_float2(acc[mi][ni][0], acc[mi][ni][1]);
                *(float2*)(out + (size_t)r1 * MN + col) =
                    make_float2(acc[mi][ni][2], acc[mi][ni][3]);
            }
        }
    }
}

extern "C" void kernel_launch(void* const* d_in, const int* in_sizes, int n_in, void* d_out,
                              int out_size) {
    const float* x = (const float*)d_in[0];
    float* out = (float*)d_out;

    cudaFuncSetAttribute(dct_gemm_kernel<0>, cudaFuncAttributeMaxDynamicSharedMemorySize, SMEM_SZ);
    cudaFuncSetAttribute(dct_gemm_kernel<1>, cudaFuncAttributeMaxDynamicSharedMemorySize, SMEM_SZ);

    fill_dct_split_kernel<<<(MN * MN / 4) / 256, 256>>>();
    convert_x_kernel<<<(MN * MN / 4) / 256, 256>>>(x);

    dim3 grid(MN / BN, MN / BM);  // (16, 32)
    dct_gemm_kernel<0><<<grid, 512, SMEM_SZ>>>(nullptr);
    dct_gemm_kernel<1><<<grid, 512, SMEM_SZ>>>(out);
}

// round 13
// speedup vs baseline: 1.0517x; 1.0517x over previous
#include <cuda_runtime.h>
#include <cuda_bf16.h>
#include <cstdint>

// 2D DCT-II (4096x4096) as two NT GEMMs on mma.sync (HMMA) tensor cores.
//   T = gemm_nt(D, X);  Y = gemm_nt(D, T);   C[i][j] = sum_k A[i][k]*B[j][k]
// fp32 emulated via bf16 split: C = Ah*Bh + Ah*Bl + Al*Bh (fp32 reg accum).
// R12: break the per-iter convoy — fragment double-buffering across k16
// steps + 4-stage cp.async pipeline (wait_group 2). Shape = R10 best
// (128x128 tile, 8 warps, 64x32 warp tiles).

constexpr int MN = 4096;
constexpr int BM = 128, BN = 128, BK = 32;
constexpr int NC = MN / BK;  // 128 k-iterations
constexpr int STAGES = 4;

constexpr uint32_t ROWB = 80;                   // 64B data + 16B pad (conflict-free ldmatrix)
constexpr uint32_t TILE_B = 128 * ROWB;         // 10240 B per operand tile
constexpr uint32_t OFF_AH = 0;
constexpr uint32_t OFF_AL = TILE_B;
constexpr uint32_t OFF_BH = 2 * TILE_B;
constexpr uint32_t OFF_BL = 3 * TILE_B;
constexpr uint32_t STAGE_B = 4 * TILE_B;        // 40960 B per stage
constexpr uint32_t SMEM_SZ = STAGES * STAGE_B;  // 163840 B

// raw-bf16 global scratch (ushort bit patterns)
__device__ __align__(256) unsigned short g_Dhi[(size_t)MN * MN];
__device__ __align__(256) unsigned short g_Dlo[(size_t)MN * MN];
__device__ __align__(256) unsigned short g_Xhi[(size_t)MN * MN];
__device__ __align__(256) unsigned short g_Xlo[(size_t)MN * MN];
__device__ __align__(256) unsigned short g_Thi[(size_t)MN * MN];
__device__ __align__(256) unsigned short g_Tlo[(size_t)MN * MN];

// ---------------- PTX helpers ----------------
__device__ __forceinline__ uint32_t smem_u32(const void* p) {
    uint32_t a;
    asm("{ .reg .u64 t; cvta.to.shared.u64 t, %1; cvt.u32.u64 %0, t; }" : "=r"(a) : "l"(p));
    return a;
}
__device__ __forceinline__ void cp16(uint32_t dst, const void* src) {
    asm volatile("cp.async.cg.shared.global [%0], [%1], 16;" ::"r"(dst), "l"(src) : "memory");
}
__device__ __forceinline__ void cp_commit() { asm volatile("cp.async.commit_group;" ::: "memory"); }
__device__ __forceinline__ void cp_wait2() { asm volatile("cp.async.wait_group 2;" ::: "memory"); }

__device__ __forceinline__ void ldsm4(uint32_t* r, uint32_t addr) {
    asm volatile("ldmatrix.sync.aligned.m8n8.x4.shared.b16 {%0,%1,%2,%3}, [%4];"
                 : "=r"(r[0]), "=r"(r[1]), "=r"(r[2]), "=r"(r[3])
                 : "r"(addr));
}
__device__ __forceinline__ void mma_bf16(float* c, const uint32_t* a, uint32_t b0, uint32_t b1) {
    asm volatile(
        "mma.sync.aligned.m16n8k16.row.col.f32.bf16.bf16.f32 "
        "{%0,%1,%2,%3}, {%4,%5,%6,%7}, {%8,%9}, {%0,%1,%2,%3};"
        : "+f"(c[0]), "+f"(c[1]), "+f"(c[2]), "+f"(c[3])
        : "r"(a[0]), "r"(a[1]), "r"(a[2]), "r"(a[3]), "r"(b0), "r"(b1));
}

// ---------------- fill / convert ----------------
__device__ __forceinline__ void split_bf16(float v, unsigned short& h, unsigned short& l) {
    __nv_bfloat16 bh = __float2bfloat16_rn(v);
    float fh = __bfloat162float(bh);
    __nv_bfloat16 bl = __float2bfloat16_rn(v - fh);
    h = __bfloat16_as_ushort(bh);
    l = __bfloat16_as_ushort(bl);
}

__global__ void fill_dct_split_kernel() {
    unsigned idx = blockIdx.x * blockDim.x + threadIdx.x;
    unsigned i4 = idx * 4;
    unsigned k = i4 >> 12;
    unsigned m0 = i4 & (MN - 1);
    unsigned short h[4], l[4];
#pragma unroll
    for (int j = 0; j < 4; j++) {
        unsigned m = m0 + j;
        unsigned t = (k * (2u * m + 1u)) & (4u * MN - 1u);
        float c = cospif((float)t * (1.0f / (2.0f * (float)MN)));
        split_bf16(c, h[j], l[j]);
    }
    uint2 ph = make_uint2((uint32_t)h[0] | ((uint32_t)h[1] << 16),
                          (uint32_t)h[2] | ((uint32_t)h[3] << 16));
    uint2 pl = make_uint2((uint32_t)l[0] | ((uint32_t)l[1] << 16),
                          (uint32_t)l[2] | ((uint32_t)l[3] << 16));
    ((uint2*)g_Dhi)[idx] = ph;
    ((uint2*)g_Dlo)[idx] = pl;
}

__global__ void convert_x_kernel(const float* __restrict__ x) {
    unsigned idx = blockIdx.x * blockDim.x + threadIdx.x;
    float4 v = ((const float4*)x)[idx];
    unsigned short h[4], l[4];
    split_bf16(v.x, h[0], l[0]);
    split_bf16(v.y, h[1], l[1]);
    split_bf16(v.z, h[2], l[2]);
    split_bf16(v.w, h[3], l[3]);
    uint2 ph = make_uint2((uint32_t)h[0] | ((uint32_t)h[1] << 16),
                          (uint32_t)h[2] | ((uint32_t)h[3] << 16));
    uint2 pl = make_uint2((uint32_t)l[0] | ((uint32_t)l[1] << 16),
                          (uint32_t)l[2] | ((uint32_t)l[3] << 16));
    ((uint2*)g_Xhi)[idx] = ph;
    ((uint2*)g_Xlo)[idx] = pl;
}

// ---------------- GEMM ----------------
// MODE 0: B = Xsplit, C -> Tsplit (bf16 hi/lo)
// MODE 1: B = Tsplit, C -> out (fp32)
template <int MODE>
__global__ void __launch_bounds__(256, 1) dct_gemm_kernel(float* __restrict__ out) {
    extern __shared__ __align__(128) char smem[];
    const uint32_t sbase = smem_u32(smem);
    const int tid = threadIdx.x;
    const int lane = tid & 31;
    const int wid = tid >> 5;
    const int wm = wid & 1;   // 2 warps along M (64 rows each)
    const int wn = wid >> 1;  // 4 warps along N (32 cols each)
    const int ntile = blockIdx.x;
    const int mtile = blockIdx.y;

    const unsigned short* __restrict__ Ah = g_Dhi;
    const unsigned short* __restrict__ Al = g_Dlo;
    const unsigned short* __restrict__ Bh = (MODE == 0) ? g_Xhi : g_Thi;
    const unsigned short* __restrict__ Bl = (MODE == 0) ? g_Xlo : g_Tlo;

    // ---- loader geometry: each thread moves 2 x 16B per operand tile ----
    const int row0 = tid >> 2;  // 0..63
    const int c0 = tid & 3;     // 16B chunk within 64B row
    const uint32_t d0 = (uint32_t)row0 * ROWB + (uint32_t)c0 * 16;
    const uint32_t d1 = d0 + 64 * ROWB;
    const size_t aoff = (size_t)(mtile * BM + row0) * MN + c0 * 8;
    const size_t boff = (size_t)(ntile * BN + row0) * MN + c0 * 8;
    const size_t rstep = (size_t)64 * MN;

    auto load_iter = [&](int it, int s) {
        const uint32_t sb = sbase + (uint32_t)s * STAGE_B;
        const size_t ko = (size_t)it * BK;
        cp16(sb + OFF_AH + d0, Ah + aoff + ko);
        cp16(sb + OFF_AH + d1, Ah + aoff + rstep + ko);
        cp16(sb + OFF_AL + d0, Al + aoff + ko);
        cp16(sb + OFF_AL + d1, Al + aoff + rstep + ko);
        cp16(sb + OFF_BH + d0, Bh + boff + ko);
        cp16(sb + OFF_BH + d1, Bh + boff + rstep + ko);
        cp16(sb + OFF_BL + d0, Bl + boff + ko);
        cp16(sb + OFF_BL + d1, Bl + boff + rstep + ko);
    };

    // ---- ldmatrix per-lane address offsets ----
    const int mt = lane >> 3;
    // A x4: mat0=(m0-7,k0-7) mat1=(m8-15,k0-7) mat2=(m0-7,k8-15) mat3=(m8-15,k8-15)
    const uint32_t a_off = (uint32_t)(wm * 64 + (mt & 1) * 8 + (lane & 7)) * ROWB +
                           (uint32_t)((mt >> 1) * 16);
    // B x4: mat0=(n0-7,k0-7) mat1=(n0-7,k8-15) mat2=(n8-15,k0-7) mat3=(n8-15,k8-15)
    const uint32_t b_off = (uint32_t)(wn * 32 + (mt >> 1) * 8 + (lane & 7)) * ROWB +
                           (uint32_t)((mt & 1) * 16);

    float acc[4][4][4];
#pragma unroll
    for (int i = 0; i < 4; i++)
#pragma unroll
        for (int j = 0; j < 4; j++)
#pragma unroll
            for (int q = 0; q < 4; q++) acc[i][j][q] = 0.0f;

    // double-buffered fragments across the two k16 steps of one iter
    uint32_t ah[2][4][4], al[2][4][4], bh[2][2][4], bl[2][2][4];

    auto load_frags = [&](uint32_t sb, int buf, int ks) {
        const uint32_t ck = (uint32_t)ks * 32;
#pragma unroll
        for (int mi = 0; mi < 4; mi++) {
            ldsm4(ah[buf][mi], sb + OFF_AH + a_off + (uint32_t)mi * (16 * ROWB) + ck);
            ldsm4(al[buf][mi], sb + OFF_AL + a_off + (uint32_t)mi * (16 * ROWB) + ck);
        }
#pragma unroll
        for (int bp = 0; bp < 2; bp++) {
            ldsm4(bh[buf][bp], sb + OFF_BH + b_off + (uint32_t)bp * (16 * ROWB) + ck);
            ldsm4(bl[buf][bp], sb + OFF_BL + b_off + (uint32_t)bp * (16 * ROWB) + ck);
        }
    };
    auto mma_frags = [&](int buf) {
#pragma unroll
        for (int mi = 0; mi < 4; mi++)
#pragma unroll
            for (int ni = 0; ni < 4; ni++) {
                const int bp = ni >> 1, pr = (ni & 1) * 2;
                mma_bf16(acc[mi][ni], ah[buf][mi], bh[buf][bp][pr], bh[buf][bp][pr + 1]);
                mma_bf16(acc[mi][ni], ah[buf][mi], bl[buf][bp][pr], bl[buf][bp][pr + 1]);
                mma_bf16(acc[mi][ni], al[buf][mi], bh[buf][bp][pr], bh[buf][bp][pr + 1]);
            }
    };

    // prologue: stages 0,1,2 in flight
    load_iter(0, 0);
    cp_commit();
    load_iter(1, 1);
    cp_commit();
    load_iter(2, 2);
    cp_commit();

    for (int it = 0; it < NC; ++it) {
        cp_wait2();       // groups pending: it,it+1,it+2 -> group `it` complete
        __syncthreads();  // data visible; all warps done with stage (it-1)%S

        if (it + 3 < NC) load_iter(it + 3, (it + 3) % STAGES);
        cp_commit();  // empty groups near the end keep wait accounting uniform

        const uint32_t sb = sbase + (uint32_t)(it % STAGES) * STAGE_B;
        // ks=0 frags, then overlap ks=1 ldmatrix with ks=0 MMAs
        load_frags(sb, 0, 0);
        load_frags(sb, 1, 1);
        mma_frags(0);
        mma_frags(1);
    }

    // ---- epilogue ----
    const int g = lane >> 2;
    const int cpair = (lane & 3) * 2;
#pragma unroll
    for (int mi = 0; mi < 4; mi++) {
#pragma unroll
        for (int ni = 0; ni < 4; ni++) {
            const int r0 = mtile * BM + wm * 64 + mi * 16 + g;
            const int r1 = r0 + 8;
            const int col = ntile * BN + wn * 32 + ni * 8 + cpair;
            if (MODE == 0) {
                unsigned short h0, l0, h1, l1;
                split_bf16(acc[mi][ni][0], h0, l0);
                split_bf16(acc[mi][ni][1], h1, l1);
                *(uint32_t*)(g_Thi + (size_t)r0 * MN + col) = (uint32_t)h0 | ((uint32_t)h1 << 16);
                *(uint32_t*)(g_Tlo + (size_t)r0 * MN + col) = (uint32_t)l0 | ((uint32_t)l1 << 16);
                split_bf16(acc[mi][ni][2], h0, l0);
                split_bf16(acc[mi][ni][3], h1, l1);
                *(uint32_t*)(g_Thi + (size_t)r1 * MN + col) = (uint32_t)h0 | ((uint32_t)h1 << 16);
                *(uint32_t*)(g_Tlo + (size_t)r1 * MN + col) = (uint32_t)l0 | ((uint32_t)l1 << 16);
            } else {
                *(float2*)(out + (size_t)r0 * MN + col) =
                    make_float2(acc[mi][ni][0], acc[mi][ni][1]);
                *(float2*)(out + (size_t)r1 * MN + col) =
                    make_float2(acc[mi][ni][2], acc[mi][ni][3]);
            }
        }
    }
}

extern "C" void kernel_launch(void* const* d_in, const int* in_sizes, int n_in, void* d_out,
                              int out_size) {
    const float* x = (const float*)d_in[0];
    float* out = (float*)d_out;

    cudaFuncSetAttribute(dct_gemm_kernel<0>, cudaFuncAttributeMaxDynamicSharedMemorySize, SMEM_SZ);
    cudaFuncSetAttribute(dct_gemm_kernel<1>, cudaFuncAttributeMaxDynamicSharedMemorySize, SMEM_SZ);

    fill_dct_split_kernel<<<(MN * MN / 4) / 256, 256>>>();
    convert_x_kernel<<<(MN * MN / 4) / 256, 256>>>(x);

    dim3 grid(MN / BN, MN / BM);  // (32, 32)
    dct_gemm_kernel<0><<<grid, 256, SMEM_SZ>>>(nullptr);
    dct_gemm_kernel<1><<<grid, 256, SMEM_SZ>>>(out);
}